// round 2
// baseline (speedup 1.0000x reference)
#include <cuda_runtime.h>
#include <cstdint>

// Problem constants
#define B_     4
#define NQ     2048
#define DQ     1024
#define NK     1024
#define DC     768
#define HEADS  16
#define DH     64
#define INNER  1024   // HEADS*DH

// Intermediate buffers (static device globals — no allocation allowed)
__device__ float g_q [(size_t)B_ * NQ * INNER];   // 33.5 MB
__device__ float g_k [(size_t)B_ * NK * INNER];   // 16.8 MB
__device__ float g_v [(size_t)B_ * NK * INNER];   // 16.8 MB
__device__ float g_ao[(size_t)B_ * NQ * INNER];   // 33.5 MB

// ---------------------------------------------------------------------------
// SGEMM: C[M,N] = A[M,K] @ B[K,N] (+ bias[N]).  Tiles 128x128x8, 256 threads,
// 8x8 microtile. Requires M%128==0, N%128==0, K%8==0 (true for all our shapes).
// ---------------------------------------------------------------------------
template <bool BIAS>
__global__ __launch_bounds__(256)
void sgemm_kernel(const float* __restrict__ A, const float* __restrict__ Bm,
                  const float* __restrict__ bias, float* __restrict__ C,
                  int M, int N, int K)
{
    __shared__ float As[8 * 132];   // transposed: As[k][m], pad 132 keeps f4 align
    __shared__ float Bs[8 * 128];   // Bs[k][n]

    const int tid  = threadIdx.x;
    const int tx   = tid & 15;      // 0..15 -> col group
    const int ty   = tid >> 4;      // 0..15 -> row group
    const int row0 = blockIdx.y * 128;
    const int col0 = blockIdx.x * 128;

    const int ar   = tid >> 1;          // 0..127
    const int ac4  = (tid & 1) << 2;    // 0 or 4
    const int bkr  = tid >> 5;          // 0..7
    const int bc4  = (tid & 31) << 2;   // 0..124

    float acc[8][8];
#pragma unroll
    for (int i = 0; i < 8; i++)
#pragma unroll
        for (int j = 0; j < 8; j++) acc[i][j] = 0.0f;

    for (int k0 = 0; k0 < K; k0 += 8) {
        float4 av = *(const float4*)(A  + (size_t)(row0 + ar) * K + k0 + ac4);
        float4 bv = *(const float4*)(Bm + (size_t)(k0 + bkr) * N + col0 + bc4);

        __syncthreads();
        As[(ac4 + 0) * 132 + ar] = av.x;
        As[(ac4 + 1) * 132 + ar] = av.y;
        As[(ac4 + 2) * 132 + ar] = av.z;
        As[(ac4 + 3) * 132 + ar] = av.w;
        *(float4*)&Bs[bkr * 128 + bc4] = bv;
        __syncthreads();

#pragma unroll
        for (int kk = 0; kk < 8; kk++) {
            float4 a0 = *(const float4*)&As[kk * 132 + ty * 8];
            float4 a1 = *(const float4*)&As[kk * 132 + ty * 8 + 4];
            float4 b0 = *(const float4*)&Bs[kk * 128 + tx * 8];
            float4 b1 = *(const float4*)&Bs[kk * 128 + tx * 8 + 4];
            float af[8] = {a0.x, a0.y, a0.z, a0.w, a1.x, a1.y, a1.z, a1.w};
            float bf[8] = {b0.x, b0.y, b0.z, b0.w, b1.x, b1.y, b1.z, b1.w};
#pragma unroll
            for (int i = 0; i < 8; i++)
#pragma unroll
                for (int j = 0; j < 8; j++)
                    acc[i][j] = fmaf(af[i], bf[j], acc[i][j]);
        }
    }

#pragma unroll
    for (int i = 0; i < 8; i++) {
        const int row = row0 + ty * 8 + i;
        float* cp = C + (size_t)row * N + col0 + tx * 8;
        float4 r0 = make_float4(acc[i][0], acc[i][1], acc[i][2], acc[i][3]);
        float4 r1 = make_float4(acc[i][4], acc[i][5], acc[i][6], acc[i][7]);
        if (BIAS) {
            const float* bp = bias + col0 + tx * 8;
            r0.x += bp[0]; r0.y += bp[1]; r0.z += bp[2]; r0.w += bp[3];
            r1.x += bp[4]; r1.y += bp[5]; r1.z += bp[6]; r1.w += bp[7];
        }
        *(float4*)(cp)     = r0;
        *(float4*)(cp + 4) = r1;
    }
}

// ---------------------------------------------------------------------------
// Flash attention: per (128 q-rows, head, batch). 256 threads.
// Online softmax, K/V tiled in chunks of 64 keys, dh = 64.
// Smem: Qs[64kk][128r+4], Ks[64kk][64key+4], Vs[64key][64c+4], Ps[64key][128r+4]
// ---------------------------------------------------------------------------
#define QS_PITCH 132
#define KS_PITCH 68
#define VS_PITCH 68
#define PS_PITCH 132
#define ATTN_SMEM_FLOATS (64*QS_PITCH + 64*KS_PITCH + 64*VS_PITCH + 64*PS_PITCH)
#define ATTN_SMEM_BYTES  (ATTN_SMEM_FLOATS * 4)

__global__ __launch_bounds__(256)
void attn_kernel(const float* __restrict__ q, const float* __restrict__ kg,
                 const float* __restrict__ vg, float* __restrict__ o)
{
    const int tid = threadIdx.x;
    const int tx  = tid & 15;   // 4 output cols: 4*tx..4*tx+3
    const int ty  = tid >> 4;   // 8 output rows: 8*ty..8*ty+7
    const int q0  = blockIdx.x * 128;
    const int h   = blockIdx.y;
    const int b   = blockIdx.z;

    extern __shared__ float sm[];
    float* Qs = sm;
    float* Ks = Qs + 64 * QS_PITCH;
    float* Vs = Ks + 64 * KS_PITCH;
    float* Ps = Vs + 64 * VS_PITCH;

    // Load Q tile [128 rows x 64 dh], store transposed Qs[kk][row]
    const size_t qbase = ((size_t)b * NQ + q0) * INNER + h * DH;
    for (int i = tid; i < 128 * 16; i += 256) {
        int r = i >> 4, c4 = (i & 15) << 2;
        float4 t = *(const float4*)(q + qbase + (size_t)r * INNER + c4);
        Qs[(c4 + 0) * QS_PITCH + r] = t.x;
        Qs[(c4 + 1) * QS_PITCH + r] = t.y;
        Qs[(c4 + 2) * QS_PITCH + r] = t.z;
        Qs[(c4 + 3) * QS_PITCH + r] = t.w;
    }

    float acc[8][4];
    float mrow[8], lrow[8];
#pragma unroll
    for (int i = 0; i < 8; i++) {
        mrow[i] = -1e30f; lrow[i] = 0.0f;
#pragma unroll
        for (int j = 0; j < 4; j++) acc[i][j] = 0.0f;
    }
    const float SCALE = 0.125f;  // 1/sqrt(64)

    for (int kt = 0; kt < NK; kt += 64) {
        __syncthreads();   // Q ready (first iter) / previous tile's PV reads done
        const size_t kbase = ((size_t)b * NK + kt) * INNER + h * DH;
        for (int i = tid; i < 64 * 16; i += 256) {
            int key = i >> 4, c4 = (i & 15) << 2;
            float4 t = *(const float4*)(kg + kbase + (size_t)key * INNER + c4);
            Ks[(c4 + 0) * KS_PITCH + key] = t.x;
            Ks[(c4 + 1) * KS_PITCH + key] = t.y;
            Ks[(c4 + 2) * KS_PITCH + key] = t.z;
            Ks[(c4 + 3) * KS_PITCH + key] = t.w;
            float4 u = *(const float4*)(vg + kbase + (size_t)key * INNER + c4);
            *(float4*)&Vs[key * VS_PITCH + c4] = u;
        }
        __syncthreads();

        // S = Q @ K^T  (128 x 64), each thread 8x4
        float s[8][4];
#pragma unroll
        for (int i = 0; i < 8; i++)
#pragma unroll
            for (int j = 0; j < 4; j++) s[i][j] = 0.0f;

#pragma unroll 8
        for (int kk = 0; kk < 64; kk++) {
            float4 a0 = *(const float4*)&Qs[kk * QS_PITCH + ty * 8];
            float4 a1 = *(const float4*)&Qs[kk * QS_PITCH + ty * 8 + 4];
            float4 bk = *(const float4*)&Ks[kk * KS_PITCH + tx * 4];
            float af[8] = {a0.x, a0.y, a0.z, a0.w, a1.x, a1.y, a1.z, a1.w};
            float bf[4] = {bk.x, bk.y, bk.z, bk.w};
#pragma unroll
            for (int i = 0; i < 8; i++)
#pragma unroll
                for (int j = 0; j < 4; j++)
                    s[i][j] = fmaf(af[i], bf[j], s[i][j]);
        }

        // Online softmax per row; row owned by 16 consecutive lanes (same ty)
#pragma unroll
        for (int i = 0; i < 8; i++) {
            float v0 = s[i][0] * SCALE, v1 = s[i][1] * SCALE;
            float v2 = s[i][2] * SCALE, v3 = s[i][3] * SCALE;
            float mx = fmaxf(fmaxf(v0, v1), fmaxf(v2, v3));
#pragma unroll
            for (int off = 8; off >= 1; off >>= 1)
                mx = fmaxf(mx, __shfl_xor_sync(0xffffffffu, mx, off));
            float mnew = fmaxf(mrow[i], mx);
            float corr = __expf(mrow[i] - mnew);
            float p0 = __expf(v0 - mnew), p1 = __expf(v1 - mnew);
            float p2 = __expf(v2 - mnew), p3 = __expf(v3 - mnew);
            float psum = (p0 + p1) + (p2 + p3);
#pragma unroll
            for (int off = 8; off >= 1; off >>= 1)
                psum += __shfl_xor_sync(0xffffffffu, psum, off);
            lrow[i] = lrow[i] * corr + psum;
            mrow[i] = mnew;
            acc[i][0] *= corr; acc[i][1] *= corr;
            acc[i][2] *= corr; acc[i][3] *= corr;
            // store P transposed: Ps[key][row]
            Ps[(tx * 4 + 0) * PS_PITCH + ty * 8 + i] = p0;
            Ps[(tx * 4 + 1) * PS_PITCH + ty * 8 + i] = p1;
            Ps[(tx * 4 + 2) * PS_PITCH + ty * 8 + i] = p2;
            Ps[(tx * 4 + 3) * PS_PITCH + ty * 8 + i] = p3;
        }
        __syncthreads();

        // O += P @ V  (128 x 64 over 64 keys)
#pragma unroll 8
        for (int key = 0; key < 64; key++) {
            float4 a0 = *(const float4*)&Ps[key * PS_PITCH + ty * 8];
            float4 a1 = *(const float4*)&Ps[key * PS_PITCH + ty * 8 + 4];
            float4 bv = *(const float4*)&Vs[key * VS_PITCH + tx * 4];
            float af[8] = {a0.x, a0.y, a0.z, a0.w, a1.x, a1.y, a1.z, a1.w};
            float bf[4] = {bv.x, bv.y, bv.z, bv.w};
#pragma unroll
            for (int i = 0; i < 8; i++)
#pragma unroll
                for (int j = 0; j < 4; j++)
                    acc[i][j] = fmaf(af[i], bf[j], acc[i][j]);
        }
    }

    // Epilogue: normalize and write
    const size_t obase = ((size_t)b * NQ + q0) * INNER + h * DH;
#pragma unroll
    for (int i = 0; i < 8; i++) {
        float inv = 1.0f / lrow[i];
        float4 r = make_float4(acc[i][0] * inv, acc[i][1] * inv,
                               acc[i][2] * inv, acc[i][3] * inv);
        *(float4*)(o + obase + (size_t)(ty * 8 + i) * INNER + tx * 4) = r;
    }
}

// ---------------------------------------------------------------------------
// Launch
// ---------------------------------------------------------------------------
extern "C" void kernel_launch(void* const* d_in, const int* in_sizes, int n_in,
                              void* d_out, int out_size)
{
    const float* x   = (const float*)d_in[0];
    const float* ctx = (const float*)d_in[1];
    const float* Wq  = (const float*)d_in[2];
    const float* Wk  = (const float*)d_in[3];
    const float* Wv  = (const float*)d_in[4];
    const float* Wo  = (const float*)d_in[5];
    const float* bo  = (const float*)d_in[6];
    float* out = (float*)d_out;

    float *q, *k, *v, *ao;
    cudaGetSymbolAddress((void**)&q,  g_q);
    cudaGetSymbolAddress((void**)&k,  g_k);
    cudaGetSymbolAddress((void**)&v,  g_v);
    cudaGetSymbolAddress((void**)&ao, g_ao);

    cudaFuncSetAttribute(attn_kernel,
                         cudaFuncAttributeMaxDynamicSharedMemorySize,
                         ATTN_SMEM_BYTES);

    // 1) Q = x @ Wq            [8192,1024] x [1024,1024]
    sgemm_kernel<false><<<dim3(INNER / 128, (B_ * NQ) / 128), 256>>>(
        x, Wq, nullptr, q, B_ * NQ, INNER, DQ);
    // 2) K = ctx @ Wk          [4096,768] x [768,1024]
    sgemm_kernel<false><<<dim3(INNER / 128, (B_ * NK) / 128), 256>>>(
        ctx, Wk, nullptr, k, B_ * NK, INNER, DC);
    // 3) V = ctx @ Wv
    sgemm_kernel<false><<<dim3(INNER / 128, (B_ * NK) / 128), 256>>>(
        ctx, Wv, nullptr, v, B_ * NK, INNER, DC);
    // 4) attention
    attn_kernel<<<dim3(NQ / 128, HEADS, B_), 256, ATTN_SMEM_BYTES>>>(q, k, v, ao);
    // 5) out = ao @ Wo + bo
    sgemm_kernel<true><<<dim3(DQ / 128, (B_ * NQ) / 128), 256>>>(
        ao, Wo, bo, out, B_ * NQ, DQ, INNER);
}